// round 1
// baseline (speedup 1.0000x reference)
#include <cuda_runtime.h>

static constexpr int B_  = 16;
static constexpr int H_  = 2048;
static constexpr int I_  = 1024;
static constexpr int NT  = 512;   // threads per block; each thread owns 4 contiguous h

__device__ __forceinline__ float flg2(float x){ float r; asm("lg2.approx.f32 %0,%1;" : "=f"(r) : "f"(x)); return r; }
__device__ __forceinline__ float frcp(float x){ float r; asm("rcp.approx.f32 %0,%1;" : "=f"(r) : "f"(x)); return r; }
__device__ __forceinline__ float fex2(float x){ float r; asm("ex2.approx.f32 %0,%1;" : "=f"(r) : "f"(x)); return r; }

__global__ __launch_bounds__(NT) void reservoir_cell_kernel(
    const float* __restrict__ x_t,         // (B, I)
    const float* __restrict__ h_prev,      // (B, H)
    const float* __restrict__ W_ih_w,      // (H, I)
    const float* __restrict__ W_ih_b,      // (H,)
    const float* __restrict__ W_hh,        // (H, H)
    const float* __restrict__ hh_mask,     // (H, H)
    const float* __restrict__ temperature, // (1,)
    const float* __restrict__ gumbel,      // (B, H, H) uniform(0,1)
    float* __restrict__ out)               // (B, H)
{
    __shared__ float  s_red[16];
    __shared__ float  s_ic[B_];
    __shared__ float2 s_part[16][B_];   // [warp][batch] partial (num, den)

    const int o   = blockIdx.x;
    const int tid = threadIdx.x;
    const int wid = tid >> 5;
    const int lid = tid & 31;

    const float inv_tau = 1.0f / fmaxf(temperature[0], 1e-3f);

    // ---------- phase 1: effective logits row -> exp(eff - max) kept in registers ----------
    const float4 wv = reinterpret_cast<const float4*>(W_hh    + (size_t)o * H_)[tid];
    const float4 mv = reinterpret_cast<const float4*>(hh_mask + (size_t)o * H_)[tid];
    float e0 = wv.x * mv.x * inv_tau;
    float e1 = wv.y * mv.y * inv_tau;
    float e2 = wv.z * mv.z * inv_tau;
    float e3 = wv.w * mv.w * inv_tau;

    float m = fmaxf(fmaxf(e0, e1), fmaxf(e2, e3));
    #pragma unroll
    for (int s = 16; s; s >>= 1) m = fmaxf(m, __shfl_xor_sync(0xffffffffu, m, s));
    if (lid == 0) s_red[wid] = m;
    __syncthreads();
    if (wid == 0) {
        float mm = s_red[lid & 15];
        #pragma unroll
        for (int s = 8; s; s >>= 1) mm = fmaxf(mm, __shfl_xor_sync(0xffffffffu, mm, s));
        if (lid == 0) s_red[0] = mm;
    }
    __syncthreads();
    m = s_red[0];

    const float L2E = 1.4426950408889634f;
    const float se0 = fex2((e0 - m) * L2E);
    const float se1 = fex2((e1 - m) * L2E);
    const float se2 = fex2((e2 - m) * L2E);
    const float se3 = fex2((e3 - m) * L2E);

    // ---------- phase 2: input contribution, warp w -> batch w ----------
    {
        float acc = 0.f;
        const float4* xr = reinterpret_cast<const float4*>(x_t + (size_t)wid * I_);
        const float4* wr = reinterpret_cast<const float4*>(W_ih_w + (size_t)o * I_);
        #pragma unroll
        for (int k = lid; k < I_ / 4; k += 32) {
            float4 a = xr[k];
            float4 b = wr[k];
            acc = fmaf(a.x, b.x, acc);
            acc = fmaf(a.y, b.y, acc);
            acc = fmaf(a.z, b.z, acc);
            acc = fmaf(a.w, b.w, acc);
        }
        #pragma unroll
        for (int s = 16; s; s >>= 1) acc += __shfl_xor_sync(0xffffffffu, acc, s);
        if (lid == 0) s_ic[wid] = acc + W_ih_b[o];
    }
    __syncthreads();

    // ---------- phase 3: stream gumbel noise; online fused softmax-dot ----------
    // weight_h = exp(eff_h - m) / t_h,  t_h = -log(u + 1e-10) + 1e-10
    const float NLN2 = -0.6931471805599453f;
    #pragma unroll 1
    for (int b = 0; b < B_; b++) {
        const float4 u  = reinterpret_cast<const float4*>(gumbel + ((size_t)b * H_ + o) * H_)[tid];
        const float4 hp = reinterpret_cast<const float4*>(h_prev + (size_t)b * H_)[tid];

        float num = 0.f, den = 0.f;
        const float ua[4] = {u.x, u.y, u.z, u.w};
        const float ha[4] = {hp.x, hp.y, hp.z, hp.w};
        const float sa[4] = {se0, se1, se2, se3};
        #pragma unroll
        for (int j = 0; j < 4; j++) {
            float uu = ua[j] + 1e-10f;
            float t  = fmaf(flg2(uu), NLN2, 1e-10f);          // -ln(uu) + eps  (fast path)
            float d  = uu - 1.0f;                             // exact for uu near 1
            float tc = fmaf(0.5f * d, d, -d) + 1e-10f;        // -d + d^2/2 + eps (accurate near 1)
            t = (uu > 0.998f) ? tc : t;
            float w = sa[j] * frcp(t);
            num = fmaf(w, ha[j], num);
            den += w;
        }
        #pragma unroll
        for (int s = 16; s; s >>= 1) {
            num += __shfl_xor_sync(0xffffffffu, num, s);
            den += __shfl_xor_sync(0xffffffffu, den, s);
        }
        if (lid == 0) s_part[wid][b] = make_float2(num, den);
    }
    __syncthreads();

    // ---------- phase 4: cross-warp reduce + epilogue; warp b handles batch b ----------
    if (wid < B_) {
        float num = 0.f, den = 0.f;
        if (lid < 16) {
            float2 p = s_part[lid][wid];
            num = p.x; den = p.y;
        }
        #pragma unroll
        for (int s = 16; s; s >>= 1) {
            num += __shfl_xor_sync(0xffffffffu, num, s);
            den += __shfl_xor_sync(0xffffffffu, den, s);
        }
        if (lid == 0) {
            float contrib = num / den;
            out[(size_t)wid * H_ + o] = tanhf(s_ic[wid] + contrib);
        }
    }
}

extern "C" void kernel_launch(void* const* d_in, const int* in_sizes, int n_in,
                              void* d_out, int out_size) {
    const float* x_t         = (const float*)d_in[0];
    const float* h_prev      = (const float*)d_in[1];
    const float* W_ih_w      = (const float*)d_in[2];
    const float* W_ih_b      = (const float*)d_in[3];
    const float* W_hh        = (const float*)d_in[4];
    const float* hh_mask     = (const float*)d_in[5];
    const float* temperature = (const float*)d_in[6];
    const float* gumbel      = (const float*)d_in[7];
    float* out = (float*)d_out;

    reservoir_cell_kernel<<<H_, NT>>>(x_t, h_prev, W_ih_w, W_ih_b, W_hh, hh_mask,
                                      temperature, gumbel, out);
}

// round 2
// speedup vs baseline: 1.4446x; 1.4446x over previous
#include <cuda_runtime.h>

static constexpr int B_  = 16;
static constexpr int H_  = 2048;
static constexpr int I_  = 1024;
static constexpr int NT  = 256;   // 8 warps; each thread owns 8 columns (2 float4 groups)

__device__ __forceinline__ float flg2(float x){ float r; asm("lg2.approx.f32 %0,%1;" : "=f"(r) : "f"(x)); return r; }
__device__ __forceinline__ float frcp(float x){ float r; asm("rcp.approx.f32 %0,%1;" : "=f"(r) : "f"(x)); return r; }
__device__ __forceinline__ float fex2(float x){ float r; asm("ex2.approx.f32 %0,%1;" : "=f"(r) : "f"(x)); return r; }

// weight core: w_scale = 1 / max(-ln(u)+1e-10, 1-u)
// -ln(u) via lg2.approx; max() replaces the near-1 branch: 1-u is the exact
// 1st-order value of -ln(u) near u=1 and is always <= -ln(u), so the max
// selects whichever is accurate (lg2.approx abs err 2^-22 only loses near u=1).
__device__ __forceinline__ float gw(float u) {
    const float NLN2 = -0.6931471805599453f;
    float t = fmaf(flg2(u), NLN2, 1e-10f);
    t = fmaxf(t, 1.0f - u);
    return frcp(t);
}

__global__ __launch_bounds__(NT, 5) void reservoir_cell_kernel(
    const float* __restrict__ x_t,         // (B, I)
    const float* __restrict__ h_prev,      // (B, H)
    const float* __restrict__ W_ih_w,      // (H, I)
    const float* __restrict__ W_ih_b,      // (H,)
    const float* __restrict__ W_hh,        // (H, H)
    const float* __restrict__ hh_mask,     // (H, H)
    const float* __restrict__ temperature, // (1,)
    const float* __restrict__ gumbel,      // (B, H, H) uniform(0,1)
    float* __restrict__ out)               // (B, H)
{
    __shared__ float  s_red[8];
    __shared__ float  s_ic[B_];
    __shared__ float2 s_part[8][B_];   // [warp][batch] partial (num, den)

    const int o   = blockIdx.x;
    const int tid = threadIdx.x;
    const int wid = tid >> 5;
    const int lid = tid & 31;

    // logits scale folded with log2(e) so phase-1 works directly in log2 domain
    const float s_l2 = 1.4426950408889634f / fmaxf(temperature[0], 1e-3f);

    // ---------- phase 1: row logits (log2 domain), block max, se[8] in regs ----------
    const float4* wrow = reinterpret_cast<const float4*>(W_hh    + (size_t)o * H_);
    const float4* mrow = reinterpret_cast<const float4*>(hh_mask + (size_t)o * H_);
    float4 wa = wrow[tid], wb = wrow[tid + NT];
    float4 ma = mrow[tid], mb = mrow[tid + NT];
    float e[8];
    e[0] = wa.x*ma.x*s_l2; e[1] = wa.y*ma.y*s_l2; e[2] = wa.z*ma.z*s_l2; e[3] = wa.w*ma.w*s_l2;
    e[4] = wb.x*mb.x*s_l2; e[5] = wb.y*mb.y*s_l2; e[6] = wb.z*mb.z*s_l2; e[7] = wb.w*mb.w*s_l2;

    float m = e[0];
    #pragma unroll
    for (int j = 1; j < 8; j++) m = fmaxf(m, e[j]);
    #pragma unroll
    for (int s = 16; s; s >>= 1) m = fmaxf(m, __shfl_xor_sync(0xffffffffu, m, s));
    if (lid == 0) s_red[wid] = m;
    __syncthreads();
    m = s_red[0];
    #pragma unroll
    for (int j = 1; j < 8; j++) m = fmaxf(m, s_red[j]);

    float se[8];
    #pragma unroll
    for (int j = 0; j < 8; j++) se[j] = fex2(e[j] - m);

    // ---------- phase 2: input contribution; warp w -> batches w and w+8 ----------
    {
        const float4* wr = reinterpret_cast<const float4*>(W_ih_w + (size_t)o * I_);
        const float4* x0 = reinterpret_cast<const float4*>(x_t + (size_t)wid * I_);
        const float4* x1 = reinterpret_cast<const float4*>(x_t + (size_t)(wid + 8) * I_);
        float a0 = 0.f, a1 = 0.f;
        #pragma unroll
        for (int k = lid; k < I_ / 4; k += 32) {
            float4 wv = wr[k];
            float4 v0 = x0[k];
            float4 v1 = x1[k];
            a0 = fmaf(wv.x, v0.x, a0); a0 = fmaf(wv.y, v0.y, a0);
            a0 = fmaf(wv.z, v0.z, a0); a0 = fmaf(wv.w, v0.w, a0);
            a1 = fmaf(wv.x, v1.x, a1); a1 = fmaf(wv.y, v1.y, a1);
            a1 = fmaf(wv.z, v1.z, a1); a1 = fmaf(wv.w, v1.w, a1);
        }
        #pragma unroll
        for (int s = 16; s; s >>= 1) {
            a0 += __shfl_xor_sync(0xffffffffu, a0, s);
            a1 += __shfl_xor_sync(0xffffffffu, a1, s);
        }
        if (lid == 0) {
            float bias = W_ih_b[o];
            s_ic[wid]     = a0 + bias;
            s_ic[wid + 8] = a1 + bias;
        }
    }

    // ---------- phase 3: stream gumbel; fused online softmax-dot, u double-buffered ----------
    const float4* hp = reinterpret_cast<const float4*>(h_prev);
    const float4* gu0 = reinterpret_cast<const float4*>(gumbel + (size_t)o * H_);
    // row for batch b starts at element b*H_*H_ -> float4 offset b*H_*H_/4
    const size_t bstride4 = (size_t)H_ * H_ / 4;

    float4 ua = gu0[tid], ub = gu0[tid + NT];

    #pragma unroll 1
    for (int b = 0; b < B_; b++) {
        const size_t nb4 = (size_t)((b + 1) & 15) * bstride4;
        float4 na = gu0[nb4 + tid];
        float4 nbv = gu0[nb4 + tid + NT];
        float4 ha = hp[(size_t)b * (H_ / 4) + tid];
        float4 hb = hp[(size_t)b * (H_ / 4) + tid + NT];

        float num = 0.f, den = 0.f;
        {
            float r, w;
            r = gw(ua.x); w = se[0] * r; num = fmaf(w, ha.x, num); den += w;
            r = gw(ua.y); w = se[1] * r; num = fmaf(w, ha.y, num); den += w;
            r = gw(ua.z); w = se[2] * r; num = fmaf(w, ha.z, num); den += w;
            r = gw(ua.w); w = se[3] * r; num = fmaf(w, ha.w, num); den += w;
            r = gw(ub.x); w = se[4] * r; num = fmaf(w, hb.x, num); den += w;
            r = gw(ub.y); w = se[5] * r; num = fmaf(w, hb.y, num); den += w;
            r = gw(ub.z); w = se[6] * r; num = fmaf(w, hb.z, num); den += w;
            r = gw(ub.w); w = se[7] * r; num = fmaf(w, hb.w, num); den += w;
        }
        #pragma unroll
        for (int s = 16; s; s >>= 1) {
            num += __shfl_xor_sync(0xffffffffu, num, s);
            den += __shfl_xor_sync(0xffffffffu, den, s);
        }
        if (lid == 0) s_part[wid][b] = make_float2(num, den);

        ua = na; ub = nbv;
    }
    __syncthreads();

    // ---------- phase 4: cross-warp reduce + epilogue; warp w -> batches 2w, 2w+1 ----------
    {
        const int b = 2 * wid + ((lid >> 3) & 1);   // lanes 0-7 -> 2w, lanes 8-15 -> 2w+1
        float num = 0.f, den = 0.f;
        if (lid < 16) {
            float2 p = s_part[lid & 7][b];
            num = p.x; den = p.y;
        }
        #pragma unroll
        for (int s = 4; s; s >>= 1) {
            num += __shfl_xor_sync(0xffffffffu, num, s);
            den += __shfl_xor_sync(0xffffffffu, den, s);
        }
        if (lid == 0 || lid == 8) {
            out[(size_t)b * H_ + o] = tanhf(s_ic[b] + num / den);
        }
    }
}

extern "C" void kernel_launch(void* const* d_in, const int* in_sizes, int n_in,
                              void* d_out, int out_size) {
    const float* x_t         = (const float*)d_in[0];
    const float* h_prev      = (const float*)d_in[1];
    const float* W_ih_w      = (const float*)d_in[2];
    const float* W_ih_b      = (const float*)d_in[3];
    const float* W_hh        = (const float*)d_in[4];
    const float* hh_mask     = (const float*)d_in[5];
    const float* temperature = (const float*)d_in[6];
    const float* gumbel      = (const float*)d_in[7];
    float* out = (float*)d_out;

    reservoir_cell_kernel<<<H_, NT>>>(x_t, h_prev, W_ih_w, W_ih_b, W_hh, hh_mask,
                                      temperature, gumbel, out);
}